// round 4
// baseline (speedup 1.0000x reference)
#include <cuda_runtime.h>
#include <math.h>

#define BB 64
#define QQ 2048
#define GG 64
#define CC 128
#define NT 512           // lsa threads
#define REPS (QQ/NT)

#define SCALE36 68719476736.0f      // 2^36
#define SCALE38 274877906944.0f     // 2^38
#define INF64 (1LL<<50)

// ---------------- device scratch (static, no allocation) ----------------
__device__ long long g_cost[BB][GG][QQ];   // quantized cost, scale 2^36
__device__ int       g_pred[BB][GG];
__device__ double    g_part_cls[512];
__device__ double    g_part_bbox[128], g_part_xyz[128], g_part_corr[128];
__device__ int       g_part_acc[128];

__constant__ float c_normf[10] = {1.0f, 1.0f, 1.0f, 0.1f, 0.1f,
                                  0.1f, 1.0f, 1.0f, 0.1f, 0.1f};

// normalize+clip+quantize a bbox element (double-float, FP32 pipe only)
__device__ __forceinline__ long long quant_bbox(float x, int k) {
    const double RD = 1.0 / (double)0.1f;          // compile-time folded
    const float Rh = (float)RD;
    const float Rl = (float)(RD - (double)Rh);
    float mh, ml;
    bool scaled = (k == 3 || k == 4 || k == 5 || k == 8 || k == 9);
    if (scaled) {
        mh = x * Rh;
        ml = fmaf(x, Rh, -mh);
        ml = fmaf(x, Rl, ml);
    } else { mh = x; ml = 0.0f; }
    if (mh > 100.0f)  { mh = 100.0f;  ml = 0.0f; }
    if (mh < -100.0f) { mh = -100.0f; ml = 0.0f; }
    return __float2ll_rn(mh * SCALE38) + __float2ll_rn(ml * SCALE38);
}

// ---------------- phase 1: cost matrix (df exp + int64 L1), no FP64 ----------------
__global__ __launch_bounds__(256) void cost_kernel(const float* __restrict__ cs,
                                                   const float* __restrict__ bp,
                                                   const int* __restrict__ gl,
                                                   const float* __restrict__ gb) {
    const int b = blockIdx.x >> 3;
    const int q = (blockIdx.x & 7) * 256 + threadIdx.x;
    __shared__ long long sgq[GG * 10];
    __shared__ int slab[GG];
    __shared__ float sTh[64], sTl[64];
    int t = threadIdx.x;
    if (t < 64) {                                   // 2^(t/64) as df (setup only)
        double e2 = exp2((double)t * 0.015625);
        float hv = (float)e2;
        sTh[t] = hv; sTl[t] = (float)(e2 - (double)hv);
    }
    for (int u = t; u < GG * 10; u += 256)          // quantize gt bboxes in-block
        sgq[u] = quant_bbox(gb[b * GG * 10 + u], u % 10);
    if (t < GG) slab[t] = gl[b * GG + t];
    __syncthreads();

    long long pnq[10];
    const float* bq = bp + (size_t)(b * QQ + q) * 10;
#pragma unroll
    for (int k = 0; k < 10; ++k) pnq[k] = quant_bbox(bq[k], k);

    const float* row = cs + (size_t)(b * QQ + q) * CC;
    long long* outp = &g_cost[b][0][q];

    const double C2D = 4.991591397704596e-7;        // ln2/64 - C1
    const float c2h = (float)C2D;
    const float c2l = (float)(C2D - (double)c2h);

    for (int g = 0; g < GG; ++g) {
        float xf = __ldg(row + slab[g]);
        xf = fminf(fmaxf(xf, -20.0f), 20.0f);
        float y = -xf;                              // want exp(-x)
        // --- df exp(y), y in [-20,20] ---
        float kf = rintf(y * 92.332482f);           // 64*log2(e)
        int k2 = (int)kf;
        float r1 = fmaf(kf, -0.010829925537109375f, y);   // exact (13-bit C1)
        float ph = kf * c2h;
        float pl = fmaf(kf, c2h, -ph);              // exact product tail
        float bneg = -ph;                           // TwoSum(r1, -ph)
        float s  = r1 + bneg;
        float tt = s - r1;
        float er = (r1 - (s - tt)) + (bneg - tt);
        float rh = s;
        float rl = er - pl - kf * c2l;              // |r| <= 0.00545
        float t2h = rh * rh;
        float t2l = fmaf(rh, rh, -t2h);
        t2l = fmaf(2.0f * rh, rl, t2l);
        float tail = (t2h * rh) *
            fmaf(rh, 0.041666668f, fmaf(t2h, 0.0083333338f, 0.16666667f));
        float h2 = 0.5f * t2h;
        float Ph = rh + h2;                         // Fast2Sum (|rh|>=|h2|)
        float Pe = (rh - Ph) + h2;
        float Pl = Pe + rl + 0.5f * t2l + tail;
        float Eh = 1.0f + Ph;                       // Fast2Sum with 1
        float El = ((1.0f - Eh) + Ph) + Pl;
        int n = k2 >> 6, j = k2 & 63;
        float th = sTh[j], tl = sTl[j];
        float mh2 = th * Eh;
        float ml2 = fmaf(th, Eh, -mh2);
        ml2 = fmaf(th, El, ml2);
        ml2 = fmaf(tl, Eh, ml2);
        float sc = __int_as_float((n + 127) << 23); // exact 2^n
        float eh = mh2 * sc, el = ml2 * sc;         // e = exp(-x) df
        // --- prob = 1/(1+e) df ---
        float dh = 1.0f + eh;                       // TwoSum(1, eh)
        float t3 = dh - 1.0f;
        float dl = ((1.0f - (dh - t3)) + (eh - t3)) + el;
        float q0 = 1.0f / dh;
        float w  = fmaf(q0, dh, -1.0f);             // exact residual
        w = fmaf(q0, dl, w);
        float probl = q0 * (w * w - w);             // df correction
        // cost_cls = -2*prob, quantized at 2^36 (exact power-of-2 scales)
        long long cq = __float2ll_rn(q0 * (-2.0f * SCALE36)) +
                       __float2ll_rn(probl * (-2.0f * SCALE36));
        // L1 part: exact int64
        const long long* gq = &sgq[g * 10];
        long long l1 = 0;
#pragma unroll
        for (int k = 0; k < 10; ++k) {
            long long d = pnq[k] - gq[k];
            l1 += (d < 0) ? -d : d;
        }
        outp[(size_t)g * QQ] = cq + (l1 >> 2);      // 0.25 * L1 (2^38 -> 2^36)
    }
}

// ---------------- phase 2: focal loss, all-negative form ----------------
__global__ __launch_bounds__(256) void losscls_kernel(const float* __restrict__ cs) {
    int t = blockIdx.x * 256 + threadIdx.x;
    const float4* row = (const float4*)(cs + (size_t)t * CC);
    float acc0 = 0.0f, acc1 = 0.0f;
#pragma unroll 4
    for (int k = 0; k < CC / 4; ++k) {
        float4 v = row[k];
        float xs[4] = {v.x, v.y, v.z, v.w};
#pragma unroll
        for (int u4 = 0; u4 < 4; ++u4) {
            float x = xs[u4];
            float e = __expf(-fabsf(x));
            float inv = 1.0f / (1.0f + e);
            float lp = log1pf(e);
            float p = (x >= 0.0f) ? inv : e * inv;        // sigmoid(x)
            float softp = (x > 0.0f) ? (x + lp) : lp;     // softplus(x)
            float term = softp * (0.75f * (p * p));
            if (u4 & 1) acc1 += term; else acc0 += term;
        }
    }
    double acc = (double)acc0 + (double)acc1;
    for (int off = 16; off; off >>= 1) acc += __shfl_down_sync(0xffffffffu, acc, off);
    __shared__ double ws[8];
    int lane = threadIdx.x & 31, warp = threadIdx.x >> 5;
    if (lane == 0) ws[warp] = acc;
    __syncthreads();
    if (threadIdx.x == 0) {
        double ssum = 0.0;
        for (int w = 0; w < 8; ++w) ssum += ws[w];
        g_part_cls[blockIdx.x] = ssum;
    }
}

// ---------------- phase 3: JV LSA with row-reduction + greedy init --------------
__global__ __launch_bounds__(NT) void lsa_kernel() {
    const int b = blockIdx.x, tid = threadIdx.x;
    const int lane = tid & 31, warp = tid >> 5;

    __shared__ long long sv[QQ + 1];
    __shared__ long long sminv[QQ + 1];
    __shared__ long long su[GG + 1];
    __shared__ short sp[QQ + 1];
    __shared__ short sway[QQ + 1];
    __shared__ short slist[QQ + 1];
    __shared__ unsigned char sstamp[QQ + 1];
    __shared__ short srowarg[GG + 1];
    __shared__ short spend[GG];
    __shared__ long long rp[NT / 32];
    __shared__ long long sdelta;
    __shared__ int scnt, sj0, si0, sdone, snpend;

    for (int j = tid; j <= QQ; j += NT) { sv[j] = 0; sp[j] = 0; sstamp[j] = 0; }
    __syncthreads();

    const long long* __restrict__ costb = &g_cost[b][0][0];

    // --- Phase A: row minima (u[i] = min_j a[i][j]), 16 warps over 64 rows ---
    for (int r = warp; r < GG; r += NT / 32) {
        const long long* arow = costb + (size_t)r * QQ;
        long long best = (1LL << 62);
#pragma unroll
        for (int k = 0; k < QQ / 32; ++k) {
            int j = lane + 32 * k;
            long long pk = (__ldg(arow + j) << 12) | (long long)(j + 1);
            best = (pk < best) ? pk : best;
        }
#pragma unroll
        for (int off = 16; off; off >>= 1) {
            long long o = __shfl_down_sync(0xffffffffu, best, off);
            best = (o < best) ? o : best;
        }
        if (lane == 0) {
            su[r + 1] = best >> 12;
            srowarg[r + 1] = (short)(best & 4095);
        }
    }
    __syncthreads();

    // --- Phase B: greedy assignment on tight edges ---
    if (tid == 0) {
        int np = 0;
        for (int i = 1; i <= GG; ++i) {
            int j = srowarg[i];
            if (sp[j] == 0) sp[j] = (short)i;
            else spend[np++] = (short)i;
        }
        snpend = np;
    }
    __syncthreads();

    // --- Phase C: augment remaining rows (JV Dijkstra, exact int64) ---
    const int np = snpend;
    for (int pi = 0; pi < np; ++pi) {
        const int i = spend[pi];
        if (tid == 0) { sj0 = 0; si0 = i; scnt = 1; slist[0] = 0; sp[0] = (short)i; sdone = 0; }
        __syncthreads();
        bool first = true;
        for (;;) {
            const int i0 = si0, j0c = sj0, cnt = scnt;
            const long long ui0 = su[i0];
            const long long dpre = first ? 0 : sdelta;
            const long long* arow = costb + (size_t)(i0 - 1) * QQ;
            long long av[REPS];
#pragma unroll
            for (int rep = 0; rep < REPS; rep++) av[rep] = __ldg(arow + tid + rep * NT);
            long long best = (1LL << 62);
#pragma unroll
            for (int rep = 0; rep < REPS; rep++) {
                int j = tid + 1 + rep * NT;
                if (sstamp[j] == (unsigned char)i) continue;
                long long mv = first ? INF64 : (sminv[j] - dpre);  // folded minv-=delta
                long long cur = av[rep] - ui0 - sv[j];
                if (cur < mv) { mv = cur; sway[j] = (short)j0c; }
                sminv[j] = mv;
                long long pk = (mv << 12) | (long long)j;          // lex (value, j)
                best = (pk < best) ? pk : best;
            }
#pragma unroll
            for (int off = 16; off; off >>= 1) {
                long long o = __shfl_down_sync(0xffffffffu, best, off);
                best = (o < best) ? o : best;
            }
            if (lane == 0) rp[warp] = best;
            __syncthreads();
            if (warp == 0) {
                best = (lane < NT / 32) ? rp[lane] : (1LL << 62);
#pragma unroll
                for (int off = (NT / 64); off; off >>= 1) {
                    long long o = __shfl_down_sync(0xffffffffu, best, off);
                    best = (o < best) ? o : best;
                }
                if (lane == 0) {
                    long long d = best >> 12;
                    int j1 = (int)(best & 4095);
                    sdelta = d; sj0 = j1; si0 = sp[j1];
                    sdone = (sp[j1] == 0);
                }
            }
            __syncthreads();
            const long long del = sdelta;
            const int fin = sdone;
            for (int tt = tid; tt < cnt; tt += NT) {   // exact int updates, old used set
                int jj = slist[tt];
                su[sp[jj]] += del;
                sv[jj] -= del;
            }
            if (tid == NT - 1 && !fin) {
                int j1 = sj0;
                sstamp[j1] = (unsigned char)i;
                slist[cnt] = (short)j1;
                scnt = cnt + 1;
            }
            __syncthreads();
            if (fin) break;
            first = false;
        }
        if (tid == 0) {                                // augment along way[]
            int j0 = sj0;
            while (j0) { int jn = sway[j0]; sp[j0] = sp[jn]; j0 = jn; }
        }
        __syncthreads();
    }
#pragma unroll
    for (int rep = 0; rep < REPS; rep++) {
        int j = tid + 1 + rep * NT;
        int pj = sp[j];
        if (pj) g_pred[b][pj - 1] = j - 1;
    }
}

// ---------------- phase 4: bbox losses + focal correction (warp per (b,g)) --------
__global__ __launch_bounds__(1024) void bbox_kernel(const float* __restrict__ cs,
                                                    const float* __restrict__ bp,
                                                    const int* __restrict__ gl,
                                                    const float* __restrict__ gb) {
    int blk = blockIdx.x;            // 0..127
    int b = blk >> 1;
    int warp = threadIdx.x >> 5, lane = threadIdx.x & 31;
    int g = (blk & 1) * 32 + warp;
    int q = g_pred[b][g];
    int lab = gl[b * GG + g];
    const float* r = cs + (size_t)(b * QQ + q) * CC;

    // argmax over 128, numpy first-occurrence
    float best = -INFINITY; int bi = 0;
#pragma unroll
    for (int k = 0; k < 4; ++k) {
        int c = lane + 32 * k;
        float v = r[c];
        if (v > best) { best = v; bi = c; }
    }
    for (int off = 16; off; off >>= 1) {
        float ov = __shfl_down_sync(0xffffffffu, best, off);
        int   oi = __shfl_down_sync(0xffffffffu, bi, off);
        if (ov > best || (ov == best && oi < bi)) { best = ov; bi = oi; }
    }

    double sb = 0.0, sx = 0.0;
    if (lane < 10) {
        float a  = bp[(size_t)(b * QQ + q) * 10 + lane];
        float c2 = gb[(size_t)(b * GG + g) * 10 + lane];
        float nr = c_normf[lane];
        sb = (double)fabsf(a / nr - c2 / nr);
        if (lane < 3) sx = (double)fabsf(a - c2);
    }
    double corr = 0.0;
    if (lane == 0) {                 // focal correction: pos - neg (bitwise same neg as losscls)
        float x = r[lab];
        float e = __expf(-fabsf(x));
        float inv = 1.0f / (1.0f + e);
        float lp = log1pf(e);
        float p = (x >= 0.0f) ? inv : e * inv;
        float softp = (x > 0.0f) ? (x + lp) : lp;
        float softm = (x > 0.0f) ? lp : (lp - x);
        float om = 1.0f - p;
        float neg = softp * (0.75f * (p * p));
        float pos = softm * (0.25f * (om * om));
        corr = (double)pos - (double)neg;
    }
    for (int off = 16; off; off >>= 1) {
        sb   += __shfl_down_sync(0xffffffffu, sb, off);
        sx   += __shfl_down_sync(0xffffffffu, sx, off);
        corr += __shfl_down_sync(0xffffffffu, corr, off);
    }
    __shared__ double shb[32], shx[32], shc[32];
    __shared__ int sha[32];
    if (lane == 0) { shb[warp] = sb; shx[warp] = sx; shc[warp] = corr; sha[warp] = (bi == lab); }
    __syncthreads();
    if (threadIdx.x == 0) {
        double tb = 0, tx = 0, tc = 0; int ta = 0;
        for (int w = 0; w < 32; ++w) { tb += shb[w]; tx += shx[w]; tc += shc[w]; ta += sha[w]; }
        g_part_bbox[blk] = tb; g_part_xyz[blk] = tx; g_part_corr[blk] = tc; g_part_acc[blk] = ta;
    }
}

// ---------------- phase 5: final combine ----------------
__global__ void final_kernel(float* __restrict__ out) {
    int lane = threadIdx.x;   // 32 threads
    double s = 0.0;
    for (int k = lane; k < 512; k += 32) s += g_part_cls[k];
    double corr = 0.0, sb = 0.0, sx = 0.0, ac = 0.0;
    for (int k = lane; k < 128; k += 32) {
        corr += g_part_corr[k]; sb += g_part_bbox[k]; sx += g_part_xyz[k];
        ac += (double)g_part_acc[k];
    }
    for (int off = 16; off; off >>= 1) {
        s    += __shfl_down_sync(0xffffffffu, s, off);
        corr += __shfl_down_sync(0xffffffffu, corr, off);
        sb   += __shfl_down_sync(0xffffffffu, sb, off);
        sx   += __shfl_down_sync(0xffffffffu, sx, off);
        ac   += __shfl_down_sync(0xffffffffu, ac, off);
    }
    if (lane == 0) {
        out[0] = (float)((s + corr) / 4096.0);
        out[1] = (float)(sb / 40960.0);
        out[2] = 64.0f;
        out[3] = (float)(ac / 4096.0);
        out[4] = (float)(sx / 12288.0);
    }
}

// ---------------- launch ----------------
extern "C" void kernel_launch(void* const* d_in, const int* in_sizes, int n_in,
                              void* d_out, int out_size) {
    const float* cs = (const float*)d_in[0];   // (64,2048,128) f32
    const float* bp = (const float*)d_in[1];   // (64,2048,10)  f32
    const int*   gl = (const int*)d_in[2];     // (64,64)       i32
    const float* gb = (const float*)d_in[3];   // (64,64,10)    f32
    float* out = (float*)d_out;

    cost_kernel<<<BB * 8, 256>>>(cs, bp, gl, gb);
    losscls_kernel<<<(BB * QQ) / 256, 256>>>(cs);
    lsa_kernel<<<BB, NT>>>();
    bbox_kernel<<<BB * 2, 1024>>>(cs, bp, gl, gb);
    final_kernel<<<1, 32>>>(out);
}

// round 5
// speedup vs baseline: 1.4682x; 1.4682x over previous
#include <cuda_runtime.h>
#include <math.h>

#define BB 64
#define QQ 2048
#define GG 64
#define CC 128
#define NT 512           // lsa threads
#define REPS (QQ/NT)

#define SCALE19 524288.0f           // 2^19 (bbox quant)
#define NEG2S21 (-4194304.0f)       // -2 * 2^21 (cls quant)
#define INF64 (1LL<<50)

// ---------------- device scratch (static, no allocation) ----------------
__device__ int    g_cost[BB][GG][QQ];      // quantized cost, int32, scale 2^21
__device__ int    g_pred[BB][GG];
__device__ double g_part_cls[512];
__device__ double g_part_bbox[128], g_part_xyz[128], g_part_corr[128];
__device__ int    g_part_acc[128];

__constant__ float c_normf[10] = {1.0f, 1.0f, 1.0f, 0.1f, 0.1f,
                                  0.1f, 1.0f, 1.0f, 0.1f, 0.1f};

// normalize+clip+quantize bbox element at scale 2^19 (double-float, FP32 pipe)
__device__ __forceinline__ int quant_bbox19(float x, int k) {
    const double RD = 1.0 / (double)0.1f;
    const float Rh = (float)RD;
    const float Rl = (float)(RD - (double)Rh);
    float mh, ml;
    bool scaled = (k == 3 || k == 4 || k == 5 || k == 8 || k == 9);
    if (scaled) {
        mh = x * Rh;
        ml = fmaf(x, Rh, -mh);
        ml = fmaf(x, Rl, ml);
    } else { mh = x; ml = 0.0f; }
    if (mh > 100.0f)  { mh = 100.0f;  ml = 0.0f; }
    if (mh < -100.0f) { mh = -100.0f; ml = 0.0f; }
    return __float2int_rn(mh * SCALE19) + __float2int_rn(ml * SCALE19);
}

// shared focal pieces — used bitwise-identically by losscls and bbox correction
__device__ __forceinline__ void sigparts(float x, float& p, float& lp) {
    float e = __expf(-fabsf(x));
    float inv = 1.0f / (1.0f + e);
    lp = (e < 1e-4f) ? fmaf(-0.5f * e, e, e) : __logf(1.0f + e);  // log(1+e)
    p = (x >= 0.0f) ? inv : e * inv;                              // sigmoid(x)
}
__device__ __forceinline__ float focal_neg(float x) {
    float p, lp; sigparts(x, p, lp);
    float softp = (x > 0.0f) ? (x + lp) : lp;                     // softplus(x)
    return softp * (0.75f * (p * p));
}
__device__ __forceinline__ float focal_pos(float x) {
    float p, lp; sigparts(x, p, lp);
    float softm = (x > 0.0f) ? lp : (lp - x);                     // softplus(-x)
    float om = 1.0f - p;
    return softm * (0.25f * (om * om));
}

// ---------------- phase 1: cost matrix (fp32 sigmoid + exact int32 L1) ----------
__global__ __launch_bounds__(256) void cost_kernel(const float* __restrict__ cs,
                                                   const float* __restrict__ bp,
                                                   const int* __restrict__ gl,
                                                   const float* __restrict__ gb) {
    const int b = blockIdx.x >> 3;
    const int q = (blockIdx.x & 7) * 256 + threadIdx.x;
    __shared__ int sgq[GG][10];
    __shared__ int slab[GG];
    int t = threadIdx.x;
    for (int u = t; u < GG * 10; u += 256)
        sgq[u / 10][u % 10] = quant_bbox19(gb[b * GG * 10 + u], u % 10);
    if (t < GG) slab[t] = gl[b * GG + t];
    __syncthreads();

    int pnq[10];
    const float* bq = bp + (size_t)(b * QQ + q) * 10;
#pragma unroll
    for (int k = 0; k < 10; ++k) pnq[k] = quant_bbox19(bq[k], k);

    const float* row = cs + (size_t)(b * QQ + q) * CC;
    int* outp = &g_cost[b][0][q];

    for (int g = 0; g < GG; ++g) {
        float x = __ldg(row + slab[g]);
        x = fminf(fmaxf(x, -20.0f), 20.0f);
        float e = __expf(-x);
        float p = __fdividef(1.0f, 1.0f + e);         // sigmoid
        int cq = __float2int_rn(NEG2S21 * p);         // -2*prob at 2^21
        int l1 = 0;                                   // 0.25*L1 at 2^21 == sum at 2^19
#pragma unroll
        for (int k = 0; k < 10; ++k) {
            int d = pnq[k] - sgq[g][k];
            l1 += (d < 0) ? -d : d;
        }
        outp[(size_t)g * QQ] = cq + l1;
    }
}

// ---------------- phase 2: focal loss, all-negative form ----------------
__global__ __launch_bounds__(256) void losscls_kernel(const float* __restrict__ cs) {
    int t = blockIdx.x * 256 + threadIdx.x;
    const float4* row = (const float4*)(cs + (size_t)t * CC);
    float acc0 = 0.0f, acc1 = 0.0f;
#pragma unroll 4
    for (int k = 0; k < CC / 4; ++k) {
        float4 v = row[k];
        acc0 += focal_neg(v.x);
        acc1 += focal_neg(v.y);
        acc0 += focal_neg(v.z);
        acc1 += focal_neg(v.w);
    }
    double acc = (double)acc0 + (double)acc1;
    for (int off = 16; off; off >>= 1) acc += __shfl_down_sync(0xffffffffu, acc, off);
    __shared__ double ws[8];
    int lane = threadIdx.x & 31, warp = threadIdx.x >> 5;
    if (lane == 0) ws[warp] = acc;
    __syncthreads();
    if (threadIdx.x == 0) {
        double ssum = 0.0;
        for (int w = 0; w < 8; ++w) ssum += ws[w];
        g_part_cls[blockIdx.x] = ssum;
    }
}

// ---------------- phase 3: JV LSA (row-reduce + greedy + Dijkstra), int32 costs --
__global__ __launch_bounds__(NT) void lsa_kernel() {
    const int b = blockIdx.x, tid = threadIdx.x;
    const int lane = tid & 31, warp = tid >> 5;

    __shared__ long long sv[QQ + 1];
    __shared__ long long sminv[QQ + 1];
    __shared__ long long su[GG + 1];
    __shared__ short sp[QQ + 1];
    __shared__ short sway[QQ + 1];
    __shared__ short slist[QQ + 1];
    __shared__ unsigned char sstamp[QQ + 1];
    __shared__ short srowarg[GG + 1];
    __shared__ short spend[GG];
    __shared__ long long rp[NT / 32];
    __shared__ long long sdelta;
    __shared__ int scnt, sj0, si0, sdone, snpend;

    for (int j = tid; j <= QQ; j += NT) { sv[j] = 0; sp[j] = 0; sstamp[j] = 0; }
    __syncthreads();

    const int* __restrict__ costb = &g_cost[b][0][0];

    // --- Phase A: row minima, 16 warps over 64 rows ---
    for (int r = warp; r < GG; r += NT / 32) {
        const int* arow = costb + (size_t)r * QQ;
        long long best = (1LL << 62);
#pragma unroll
        for (int k = 0; k < QQ / 32; ++k) {
            int j = lane + 32 * k;
            long long pk = ((long long)__ldg(arow + j) << 12) | (long long)(j + 1);
            best = (pk < best) ? pk : best;
        }
#pragma unroll
        for (int off = 16; off; off >>= 1) {
            long long o = __shfl_down_sync(0xffffffffu, best, off);
            best = (o < best) ? o : best;
        }
        if (lane == 0) {
            su[r + 1] = best >> 12;
            srowarg[r + 1] = (short)(best & 4095);
        }
    }
    __syncthreads();

    // --- Phase B: greedy assignment on tight edges ---
    if (tid == 0) {
        int np = 0;
        for (int i = 1; i <= GG; ++i) {
            int j = srowarg[i];
            if (sp[j] == 0) sp[j] = (short)i;
            else spend[np++] = (short)i;
        }
        snpend = np;
    }
    __syncthreads();

    // --- Phase C: augment remaining rows ---
    const int np = snpend;
    for (int pi = 0; pi < np; ++pi) {
        const int i = spend[pi];
        if (tid == 0) { sj0 = 0; si0 = i; scnt = 1; slist[0] = 0; sp[0] = (short)i; sdone = 0; }
        __syncthreads();
        bool first = true;
        for (;;) {
            const int i0 = si0, j0c = sj0, cnt = scnt;
            const long long ui0 = su[i0];
            const long long dpre = first ? 0 : sdelta;
            const int* arow = costb + (size_t)(i0 - 1) * QQ;
            int av[REPS];
#pragma unroll
            for (int rep = 0; rep < REPS; rep++) av[rep] = __ldg(arow + tid + rep * NT);
            long long best = (1LL << 62);
#pragma unroll
            for (int rep = 0; rep < REPS; rep++) {
                int j = tid + 1 + rep * NT;
                if (sstamp[j] == (unsigned char)i) continue;
                long long mv = first ? INF64 : (sminv[j] - dpre);
                long long cur = (long long)av[rep] - ui0 - sv[j];
                if (cur < mv) { mv = cur; sway[j] = (short)j0c; }
                sminv[j] = mv;
                long long pk = (mv << 12) | (long long)j;
                best = (pk < best) ? pk : best;
            }
#pragma unroll
            for (int off = 16; off; off >>= 1) {
                long long o = __shfl_down_sync(0xffffffffu, best, off);
                best = (o < best) ? o : best;
            }
            if (lane == 0) rp[warp] = best;
            __syncthreads();
            if (warp == 0) {
                best = (lane < NT / 32) ? rp[lane] : (1LL << 62);
#pragma unroll
                for (int off = (NT / 64); off; off >>= 1) {
                    long long o = __shfl_down_sync(0xffffffffu, best, off);
                    best = (o < best) ? o : best;
                }
                if (lane == 0) {
                    sdelta = best >> 12;
                    int j1 = (int)(best & 4095);
                    sj0 = j1; si0 = sp[j1];
                    sdone = (sp[j1] == 0);
                }
            }
            __syncthreads();
            const long long del = sdelta;
            const int fin = sdone;
            for (int tt = tid; tt < cnt; tt += NT) {
                int jj = slist[tt];
                su[sp[jj]] += del;
                sv[jj] -= del;
            }
            if (tid == NT - 1 && !fin) {
                int j1 = sj0;
                sstamp[j1] = (unsigned char)i;
                slist[cnt] = (short)j1;
                scnt = cnt + 1;
            }
            __syncthreads();
            if (fin) break;
            first = false;
        }
        if (tid == 0) {
            int j0 = sj0;
            while (j0) { int jn = sway[j0]; sp[j0] = sp[jn]; j0 = jn; }
        }
        __syncthreads();
    }
#pragma unroll
    for (int rep = 0; rep < REPS; rep++) {
        int j = tid + 1 + rep * NT;
        int pj = sp[j];
        if (pj) g_pred[b][pj - 1] = j - 1;
    }
}

// ---------------- phase 4: bbox losses + focal correction (warp per (b,g)) --------
__global__ __launch_bounds__(1024) void bbox_kernel(const float* __restrict__ cs,
                                                    const float* __restrict__ bp,
                                                    const int* __restrict__ gl,
                                                    const float* __restrict__ gb) {
    int blk = blockIdx.x;            // 0..127
    int b = blk >> 1;
    int warp = threadIdx.x >> 5, lane = threadIdx.x & 31;
    int g = (blk & 1) * 32 + warp;
    int q = g_pred[b][g];
    int lab = gl[b * GG + g];
    const float* r = cs + (size_t)(b * QQ + q) * CC;

    // argmax over 128, numpy first-occurrence
    float best = -INFINITY; int bi = 0;
#pragma unroll
    for (int k = 0; k < 4; ++k) {
        int c = lane + 32 * k;
        float v = r[c];
        if (v > best) { best = v; bi = c; }
    }
    for (int off = 16; off; off >>= 1) {
        float ov = __shfl_down_sync(0xffffffffu, best, off);
        int   oi = __shfl_down_sync(0xffffffffu, bi, off);
        if (ov > best || (ov == best && oi < bi)) { best = ov; bi = oi; }
    }

    double sb = 0.0, sx = 0.0;
    if (lane < 10) {
        float a  = bp[(size_t)(b * QQ + q) * 10 + lane];
        float c2 = gb[(size_t)(b * GG + g) * 10 + lane];
        float nr = c_normf[lane];
        sb = (double)fabsf(a / nr - c2 / nr);
        if (lane < 3) sx = (double)fabsf(a - c2);
    }
    double corr = 0.0;
    if (lane == 0) {                 // pos - neg, neg bitwise identical to losscls
        float x = r[lab];
        corr = (double)focal_pos(x) - (double)focal_neg(x);
    }
    for (int off = 16; off; off >>= 1) {
        sb   += __shfl_down_sync(0xffffffffu, sb, off);
        sx   += __shfl_down_sync(0xffffffffu, sx, off);
        corr += __shfl_down_sync(0xffffffffu, corr, off);
    }
    __shared__ double shb[32], shx[32], shc[32];
    __shared__ int sha[32];
    if (lane == 0) { shb[warp] = sb; shx[warp] = sx; shc[warp] = corr; sha[warp] = (bi == lab); }
    __syncthreads();
    if (threadIdx.x == 0) {
        double tb = 0, tx = 0, tc = 0; int ta = 0;
        for (int w = 0; w < 32; ++w) { tb += shb[w]; tx += shx[w]; tc += shc[w]; ta += sha[w]; }
        g_part_bbox[blk] = tb; g_part_xyz[blk] = tx; g_part_corr[blk] = tc; g_part_acc[blk] = ta;
    }
}

// ---------------- phase 5: final combine ----------------
__global__ void final_kernel(float* __restrict__ out) {
    int lane = threadIdx.x;   // 32 threads
    double s = 0.0;
    for (int k = lane; k < 512; k += 32) s += g_part_cls[k];
    double corr = 0.0, sb = 0.0, sx = 0.0, ac = 0.0;
    for (int k = lane; k < 128; k += 32) {
        corr += g_part_corr[k]; sb += g_part_bbox[k]; sx += g_part_xyz[k];
        ac += (double)g_part_acc[k];
    }
    for (int off = 16; off; off >>= 1) {
        s    += __shfl_down_sync(0xffffffffu, s, off);
        corr += __shfl_down_sync(0xffffffffu, corr, off);
        sb   += __shfl_down_sync(0xffffffffu, sb, off);
        sx   += __shfl_down_sync(0xffffffffu, sx, off);
        ac   += __shfl_down_sync(0xffffffffu, ac, off);
    }
    if (lane == 0) {
        out[0] = (float)((s + corr) / 4096.0);
        out[1] = (float)(sb / 40960.0);
        out[2] = 64.0f;
        out[3] = (float)(ac / 4096.0);
        out[4] = (float)(sx / 12288.0);
    }
}

// ---------------- launch ----------------
extern "C" void kernel_launch(void* const* d_in, const int* in_sizes, int n_in,
                              void* d_out, int out_size) {
    const float* cs = (const float*)d_in[0];   // (64,2048,128) f32
    const float* bp = (const float*)d_in[1];   // (64,2048,10)  f32
    const int*   gl = (const int*)d_in[2];     // (64,64)       i32
    const float* gb = (const float*)d_in[3];   // (64,64,10)    f32
    float* out = (float*)d_out;

    cost_kernel<<<BB * 8, 256>>>(cs, bp, gl, gb);
    losscls_kernel<<<(BB * QQ) / 256, 256>>>(cs);
    lsa_kernel<<<BB, NT>>>();
    bbox_kernel<<<BB * 2, 1024>>>(cs, bp, gl, gb);
    final_kernel<<<1, 32>>>(out);
}

// round 6
// speedup vs baseline: 3.0225x; 2.0586x over previous
#include <cuda_runtime.h>
#include <math.h>

#define BB 64
#define QQ 2048
#define GG 64
#define CC 128
#define NT 512           // lsa threads
#define REPS (QQ/NT)
#define QT 64            // q-tile per fused block
#define NQB (QQ/QT)      // 32 q-blocks per batch

#define SCALE19 524288.0f           // 2^19 (bbox quant)
#define NEG2S21 (-4194304.0f)       // -2 * 2^21 (cls quant)
#define INF64 (1LL<<50)

// ---------------- device scratch (static, no allocation) ----------------
__device__ int                g_cost[BB][GG][QQ];        // quantized cost, int32, 2^21
__device__ unsigned long long g_blockmin[BB][NQB][GG];   // per-qblock row minima (packed)
__device__ double             g_part_cls[BB * NQB];
__device__ double             g_part_bbox[BB], g_part_xyz[BB], g_part_corr[BB];
__device__ int                g_part_acc[BB];

__constant__ float c_normf[10] = {1.0f, 1.0f, 1.0f, 0.1f, 0.1f,
                                  0.1f, 1.0f, 1.0f, 0.1f, 0.1f};

// normalize+clip+quantize bbox element at scale 2^19 (double-float, FP32 pipe)
__device__ __forceinline__ int quant_bbox19(float x, int k) {
    const double RD = 1.0 / (double)0.1f;
    const float Rh = (float)RD;
    const float Rl = (float)(RD - (double)Rh);
    float mh, ml;
    bool scaled = (k == 3 || k == 4 || k == 5 || k == 8 || k == 9);
    if (scaled) {
        mh = x * Rh;
        ml = fmaf(x, Rh, -mh);
        ml = fmaf(x, Rl, ml);
    } else { mh = x; ml = 0.0f; }
    if (mh > 100.0f)  { mh = 100.0f;  ml = 0.0f; }
    if (mh < -100.0f) { mh = -100.0f; ml = 0.0f; }
    return __float2int_rn(mh * SCALE19) + __float2int_rn(ml * SCALE19);
}

// shared focal pieces — used identically by fused focal sum and bbox correction
__device__ __forceinline__ void sigparts(float x, float& p, float& lp) {
    float e = __expf(-fabsf(x));
    float inv = 1.0f / (1.0f + e);
    lp = (e < 1e-4f) ? fmaf(-0.5f * e, e, e) : __logf(1.0f + e);  // log(1+e)
    p = (x >= 0.0f) ? inv : e * inv;                              // sigmoid(x)
}
__device__ __forceinline__ float focal_neg(float x) {
    float p, lp; sigparts(x, p, lp);
    float softp = (x > 0.0f) ? (x + lp) : lp;                     // softplus(x)
    return softp * (0.75f * (p * p));
}
__device__ __forceinline__ float focal_pos(float x) {
    float p, lp; sigparts(x, p, lp);
    float softm = (x > 0.0f) ? lp : (lp - x);                     // softplus(-x)
    float om = 1.0f - p;
    return softm * (0.25f * (om * om));
}

__device__ __forceinline__ unsigned long long umin64(unsigned long long a,
                                                     unsigned long long b) {
    return (a < b) ? a : b;
}

// ======== K1: fused cost matrix + per-block row minima + focal partial ========
__global__ __launch_bounds__(256) void fused_kernel(const float* __restrict__ cs,
                                                    const float* __restrict__ bp,
                                                    const int* __restrict__ gl,
                                                    const float* __restrict__ gb) {
    const int b = blockIdx.x >> 5;          // 32 q-blocks per batch
    const int qblk = blockIdx.x & 31;
    const int qbase = qblk * QT;
    const int tid = threadIdx.x;

    __shared__ int sgq[GG][10];
    __shared__ int slab[GG];
    __shared__ int spn[QT][10];
    __shared__ int smc[GG][QT + 1];         // stride 65 -> conflict-free
    __shared__ double swred[8];

    for (int u = tid; u < GG * 10; u += 256)
        sgq[u / 10][u % 10] = quant_bbox19(gb[b * GG * 10 + u], u % 10);
    if (tid < GG) slab[tid] = gl[b * GG + tid];
    for (int u = tid; u < QT * 10; u += 256)
        spn[u / 10][u % 10] = quant_bbox19(bp[((size_t)(b * QQ) + qbase) * 10 + u], u % 10);
    __syncthreads();

    const int tx = tid & 63;                // g index
    const int ty = tid >> 6;                // 0..3
    // main: lanes = consecutive g -> gather reads consecutive cols of ONE row
    for (int qq = 0; qq < 16; ++qq) {
        int ql = ty * 16 + qq;
        float x = __ldg(cs + ((size_t)(b * QQ + qbase + ql)) * CC + slab[tx]);
        x = fminf(fmaxf(x, -20.0f), 20.0f);
        float e = __expf(-x);
        float p = __fdividef(1.0f, 1.0f + e);      // identical to R5 cost path
        int cq = __float2int_rn(NEG2S21 * p);
        int l1 = 0;
#pragma unroll
        for (int k = 0; k < 10; ++k) {
            int d = spn[ql][k] - sgq[tx][k];
            l1 += (d < 0) ? -d : d;
        }
        smc[tx][ql] = cq + l1;
    }
    __syncthreads();

    // coalesced writeback of the 64x64 tile
#pragma unroll
    for (int rep = 0; rep < 16; ++rep) {
        int idx = tid + 256 * rep;
        int g = idx >> 6, ql = idx & 63;
        g_cost[b][g][qbase + ql] = smc[g][ql];
    }
    // per-block row minima: 4 threads per g, packed sign-biased key
    {
        int g = tid >> 2, sub = tid & 3;
        unsigned long long best = ~0ULL;
#pragma unroll
        for (int k = 0; k < 16; ++k) {
            int ql = sub * 16 + k;
            int v = smc[g][ql];
            unsigned long long key =
                ((unsigned long long)((unsigned)v ^ 0x80000000u) << 12) |
                (unsigned)(qbase + ql + 1);
            best = umin64(best, key);
        }
        best = umin64(best, __shfl_down_sync(0xffffffffu, best, 2));
        best = umin64(best, __shfl_down_sync(0xffffffffu, best, 1));
        if (sub == 0) g_blockmin[b][qblk][g] = best;
    }

    // focal-neg partial over this 64-row tile (rows are L1/L2 hot)
    float acc0 = 0.0f, acc1 = 0.0f;
    const float4* base4 = (const float4*)(cs + ((size_t)(b * QQ + qbase)) * CC);
    for (int idx = tid; idx < QT * (CC / 4); idx += 256) {
        float4 v = __ldg(base4 + idx);
        acc0 += focal_neg(v.x);
        acc1 += focal_neg(v.y);
        acc0 += focal_neg(v.z);
        acc1 += focal_neg(v.w);
    }
    double acc = (double)acc0 + (double)acc1;
    for (int off = 16; off; off >>= 1) acc += __shfl_down_sync(0xffffffffu, acc, off);
    int lane = tid & 31, warp = tid >> 5;
    if (lane == 0) swred[warp] = acc;
    __syncthreads();
    if (tid == 0) {
        double s = 0.0;
        for (int w = 0; w < 8; ++w) s += swred[w];
        g_part_cls[blockIdx.x] = s;
    }
}

// ======== K2: JV LSA (blockmin-init greedy + Dijkstra) + fused bbox epilogue ====
__global__ __launch_bounds__(NT) void lsa_kernel(const float* __restrict__ cs,
                                                 const float* __restrict__ bp,
                                                 const int* __restrict__ gl,
                                                 const float* __restrict__ gb) {
    const int b = blockIdx.x, tid = threadIdx.x;
    const int lane = tid & 31, warp = tid >> 5;

    __shared__ long long sv[QQ + 1];
    __shared__ long long sminv[QQ + 1];
    __shared__ long long su[GG + 1];
    __shared__ short sp[QQ + 1];
    __shared__ short sway[QQ + 1];
    __shared__ short slist[QQ + 1];
    __shared__ unsigned char sstamp[QQ + 1];
    __shared__ short srowarg[GG + 1];
    __shared__ short spend[GG];
    __shared__ short sinv[GG];
    __shared__ unsigned long long sred[NT];
    __shared__ long long rp[NT / 32];
    __shared__ long long sdelta;
    __shared__ int scnt, sj0, si0, sdone, snpend;

    for (int j = tid; j <= QQ; j += NT) { sv[j] = 0; sp[j] = 0; sstamp[j] = 0; }

    // --- Phase A: reduce per-block row minima (2048 packed u64) ---
    {
        int g = tid & 63, grp = tid >> 6;      // 8 groups of 4 k's
        unsigned long long best = ~0ULL;
#pragma unroll
        for (int k = 0; k < 4; ++k)
            best = umin64(best, __ldg(&g_blockmin[b][grp * 4 + k][g]));
        sred[tid] = best;
    }
    __syncthreads();
    if (tid < GG) {
        unsigned long long m = sred[tid];
#pragma unroll
        for (int j = 1; j < 8; ++j) m = umin64(m, sred[tid + 64 * j]);
        int v = (int)((unsigned)(m >> 12) ^ 0x80000000u);
        su[tid + 1] = (long long)v;
        srowarg[tid + 1] = (short)(m & 4095);
    }
    __syncthreads();

    const int* __restrict__ costb = &g_cost[b][0][0];

    // --- Phase B: greedy assignment on tight edges ---
    if (tid == 0) {
        int np = 0;
        for (int i = 1; i <= GG; ++i) {
            int j = srowarg[i];
            if (sp[j] == 0) sp[j] = (short)i;
            else spend[np++] = (short)i;
        }
        snpend = np;
    }
    __syncthreads();

    // --- Phase C: augment remaining rows ---
    const int np = snpend;
    for (int pi = 0; pi < np; ++pi) {
        const int i = spend[pi];
        if (tid == 0) { sj0 = 0; si0 = i; scnt = 1; slist[0] = 0; sp[0] = (short)i; sdone = 0; }
        __syncthreads();
        bool first = true;
        for (;;) {
            const int i0 = si0, j0c = sj0, cnt = scnt;
            const long long ui0 = su[i0];
            const long long dpre = first ? 0 : sdelta;
            const int* arow = costb + (size_t)(i0 - 1) * QQ;
            int av[REPS];
#pragma unroll
            for (int rep = 0; rep < REPS; rep++) av[rep] = __ldg(arow + tid + rep * NT);
            long long best = (1LL << 62);
#pragma unroll
            for (int rep = 0; rep < REPS; rep++) {
                int j = tid + 1 + rep * NT;
                if (sstamp[j] == (unsigned char)i) continue;
                long long mv = first ? INF64 : (sminv[j] - dpre);
                long long cur = (long long)av[rep] - ui0 - sv[j];
                if (cur < mv) { mv = cur; sway[j] = (short)j0c; }
                sminv[j] = mv;
                long long pk = (mv << 12) | (long long)j;
                best = (pk < best) ? pk : best;
            }
#pragma unroll
            for (int off = 16; off; off >>= 1) {
                long long o = __shfl_down_sync(0xffffffffu, best, off);
                best = (o < best) ? o : best;
            }
            if (lane == 0) rp[warp] = best;
            __syncthreads();
            if (warp == 0) {
                best = (lane < NT / 32) ? rp[lane] : (1LL << 62);
#pragma unroll
                for (int off = (NT / 64); off; off >>= 1) {
                    long long o = __shfl_down_sync(0xffffffffu, best, off);
                    best = (o < best) ? o : best;
                }
                if (lane == 0) {
                    sdelta = best >> 12;
                    int j1 = (int)(best & 4095);
                    sj0 = j1; si0 = sp[j1];
                    sdone = (sp[j1] == 0);
                }
            }
            __syncthreads();
            const long long del = sdelta;
            const int fin = sdone;
            for (int tt = tid; tt < cnt; tt += NT) {
                int jj = slist[tt];
                su[sp[jj]] += del;
                sv[jj] -= del;
            }
            if (tid == NT - 1 && !fin) {
                int j1 = sj0;
                sstamp[j1] = (unsigned char)i;
                slist[cnt] = (short)j1;
                scnt = cnt + 1;
            }
            __syncthreads();
            if (fin) break;
            first = false;
        }
        if (tid == 0) {
            int j0 = sj0;
            while (j0) { int jn = sway[j0]; sp[j0] = sp[jn]; j0 = jn; }
        }
        __syncthreads();
    }

    // --- build g -> q map in smem ---
#pragma unroll
    for (int rep = 0; rep < REPS; rep++) {
        int j = tid + 1 + rep * NT;
        int pj = sp[j];
        if (pj) sinv[pj - 1] = (short)(j - 1);
    }
    __syncthreads();

    // --- fused bbox losses + argmax acc + focal correction (warp per g) ---
    double sb = 0.0, sx = 0.0, corr = 0.0;
    int ok = 0;
#pragma unroll
    for (int gw = 0; gw < 4; ++gw) {
        int g = gw * 16 + warp;
        int q = sinv[g];
        int lab = gl[b * GG + g];
        const float* r = cs + (size_t)(b * QQ + q) * CC;

        float best = -INFINITY; int bi = 0;
#pragma unroll
        for (int k = 0; k < 4; ++k) {
            int c = lane + 32 * k;
            float v = __ldg(r + c);
            if (v > best) { best = v; bi = c; }
        }
        for (int off = 16; off; off >>= 1) {
            float ov = __shfl_down_sync(0xffffffffu, best, off);
            int   oi = __shfl_down_sync(0xffffffffu, bi, off);
            if (ov > best || (ov == best && oi < bi)) { best = ov; bi = oi; }
        }
        if (lane == 0) ok += (bi == lab) ? 1 : 0;

        if (lane < 10) {
            float a  = bp[(size_t)(b * QQ + q) * 10 + lane];
            float c2 = gb[(size_t)(b * GG + g) * 10 + lane];
            float nr = c_normf[lane];
            sb += (double)fabsf(a / nr - c2 / nr);
            if (lane < 3) sx += (double)fabsf(a - c2);
        }
        if (lane == 0) {
            float x = __ldg(r + lab);
            corr += (double)focal_pos(x) - (double)focal_neg(x);
        }
    }
    for (int off = 16; off; off >>= 1) {
        sb   += __shfl_down_sync(0xffffffffu, sb, off);
        sx   += __shfl_down_sync(0xffffffffu, sx, off);
        corr += __shfl_down_sync(0xffffffffu, corr, off);
        ok   += __shfl_down_sync(0xffffffffu, ok, off);
    }
    __shared__ double shb[16], shx[16], shc[16];
    __shared__ int sha[16];
    if (lane == 0) { shb[warp] = sb; shx[warp] = sx; shc[warp] = corr; sha[warp] = ok; }
    __syncthreads();
    if (tid == 0) {
        double tb = 0, tx2 = 0, tc = 0; int ta = 0;
        for (int w = 0; w < 16; ++w) { tb += shb[w]; tx2 += shx[w]; tc += shc[w]; ta += sha[w]; }
        g_part_bbox[b] = tb; g_part_xyz[b] = tx2; g_part_corr[b] = tc; g_part_acc[b] = ta;
    }
}

// ======== K3: final combine ========
__global__ __launch_bounds__(256) void final_kernel(float* __restrict__ out) {
    int tid = threadIdx.x;
    double s = 0.0;
    for (int k = tid; k < BB * NQB; k += 256) s += g_part_cls[k];
    double corr = 0.0, sb = 0.0, sx = 0.0, ac = 0.0;
    if (tid < BB) {
        corr = g_part_corr[tid]; sb = g_part_bbox[tid]; sx = g_part_xyz[tid];
        ac = (double)g_part_acc[tid];
    }
    for (int off = 16; off; off >>= 1) {
        s    += __shfl_down_sync(0xffffffffu, s, off);
        corr += __shfl_down_sync(0xffffffffu, corr, off);
        sb   += __shfl_down_sync(0xffffffffu, sb, off);
        sx   += __shfl_down_sync(0xffffffffu, sx, off);
        ac   += __shfl_down_sync(0xffffffffu, ac, off);
    }
    __shared__ double w0[8], w1[8], w2[8], w3[8], w4[8];
    int lane = tid & 31, warp = tid >> 5;
    if (lane == 0) { w0[warp] = s; w1[warp] = corr; w2[warp] = sb; w3[warp] = sx; w4[warp] = ac; }
    __syncthreads();
    if (tid == 0) {
        double ts = 0, tc = 0, tb = 0, tx = 0, ta = 0;
        for (int w = 0; w < 8; ++w) { ts += w0[w]; tc += w1[w]; tb += w2[w]; tx += w3[w]; ta += w4[w]; }
        out[0] = (float)((ts + tc) / 4096.0);
        out[1] = (float)(tb / 40960.0);
        out[2] = 64.0f;
        out[3] = (float)(ta / 4096.0);
        out[4] = (float)(tx / 12288.0);
    }
}

// ---------------- launch ----------------
extern "C" void kernel_launch(void* const* d_in, const int* in_sizes, int n_in,
                              void* d_out, int out_size) {
    const float* cs = (const float*)d_in[0];   // (64,2048,128) f32
    const float* bp = (const float*)d_in[1];   // (64,2048,10)  f32
    const int*   gl = (const int*)d_in[2];     // (64,64)       i32
    const float* gb = (const float*)d_in[3];   // (64,64,10)    f32
    float* out = (float*)d_out;

    fused_kernel<<<BB * NQB, 256>>>(cs, bp, gl, gb);
    lsa_kernel<<<BB, NT>>>(cs, bp, gl, gb);
    final_kernel<<<1, 256>>>(out);
}

// round 7
// speedup vs baseline: 3.0314x; 1.0030x over previous
#include <cuda_runtime.h>
#include <math.h>

#define BB 64
#define QQ 2048
#define GG 64
#define CC 128
#define NT 512           // lsa threads
#define REPS (QQ/NT)
#define QT 64            // q-tile per fused block
#define NQB (QQ/QT)      // 32 q-blocks per batch

#define SCALE19 524288.0f           // 2^19 (bbox quant)
#define NEG2S21 (-4194304.0f)       // -2 * 2^21 (cls quant)
#define INF64 (1LL<<50)

// ---------------- device scratch (static, no allocation) ----------------
__device__ int                g_cost[BB][GG][QQ];        // quantized cost, int32, 2^21
__device__ unsigned long long g_blockmin[BB][NQB][GG];   // per-qblock row minima (packed)
__device__ double             g_part_cls[BB * NQB];
__device__ double             g_part_bbox[BB], g_part_xyz[BB], g_part_corr[BB];
__device__ int                g_part_acc[BB];
__device__ int                g_ctr;                      // last-block counter (reset each run)

__constant__ float c_normf[10] = {1.0f, 1.0f, 1.0f, 0.1f, 0.1f,
                                  0.1f, 1.0f, 1.0f, 0.1f, 0.1f};

// normalize+clip+quantize bbox element at scale 2^19 (double-float, FP32 pipe)
__device__ __forceinline__ int quant_bbox19(float x, int k) {
    const double RD = 1.0 / (double)0.1f;
    const float Rh = (float)RD;
    const float Rl = (float)(RD - (double)Rh);
    float mh, ml;
    bool scaled = (k == 3 || k == 4 || k == 5 || k == 8 || k == 9);
    if (scaled) {
        mh = x * Rh;
        ml = fmaf(x, Rh, -mh);
        ml = fmaf(x, Rl, ml);
    } else { mh = x; ml = 0.0f; }
    if (mh > 100.0f)  { mh = 100.0f;  ml = 0.0f; }
    if (mh < -100.0f) { mh = -100.0f; ml = 0.0f; }
    return __float2int_rn(mh * SCALE19) + __float2int_rn(ml * SCALE19);
}

// branch-free focal pieces: e=exp(-x), softplus(x)=x+log(1+e), softplus(-x)=log(1+e)
__device__ __forceinline__ float focal_neg_fast(float x) {
    float e = __expf(-x);
    float d = 1.0f + e;
    float p = __fdividef(1.0f, d);        // sigmoid(x)
    float lg = __logf(d);                 // log(1+e)
    return (x + lg) * (0.75f * (p * p));
}

__device__ __forceinline__ unsigned long long umin64(unsigned long long a,
                                                     unsigned long long b) {
    return (a < b) ? a : b;
}

// ======== K1: fused cost matrix + per-block row minima + focal partial ========
__global__ __launch_bounds__(256) void fused_kernel(const float* __restrict__ cs,
                                                    const float* __restrict__ bp,
                                                    const int* __restrict__ gl,
                                                    const float* __restrict__ gb) {
    const int b = blockIdx.x >> 5;          // 32 q-blocks per batch
    const int qblk = blockIdx.x & 31;
    const int qbase = qblk * QT;
    const int tid = threadIdx.x;

    __shared__ int sgq[GG][10];
    __shared__ int slab[GG];
    __shared__ int spn[QT][10];
    __shared__ int smc[GG][QT + 1];         // stride 65 -> conflict-free
    __shared__ double swred[8];

    for (int u = tid; u < GG * 10; u += 256)
        sgq[u / 10][u % 10] = quant_bbox19(gb[b * GG * 10 + u], u % 10);
    if (tid < GG) slab[tid] = gl[b * GG + tid];
    for (int u = tid; u < QT * 10; u += 256)
        spn[u / 10][u % 10] = quant_bbox19(bp[((size_t)(b * QQ) + qbase) * 10 + u], u % 10);
    __syncthreads();

    const int tx = tid & 63;                // g index
    const int ty = tid >> 6;                // 0..3
    // cost: lanes = consecutive g -> gather reads consecutive cols of ONE row
    for (int qq = 0; qq < 16; ++qq) {
        int ql = ty * 16 + qq;
        float x = __ldg(cs + ((size_t)(b * QQ + qbase + ql)) * CC + slab[tx]);
        x = fminf(fmaxf(x, -20.0f), 20.0f);
        float e = __expf(-x);
        float p = __fdividef(1.0f, 1.0f + e);      // identical to R5/R6 cost path
        int cq = __float2int_rn(NEG2S21 * p);
        int l1 = 0;
#pragma unroll
        for (int k = 0; k < 10; ++k) {
            int d = spn[ql][k] - sgq[tx][k];
            l1 += (d < 0) ? -d : d;
        }
        smc[tx][ql] = cq + l1;
    }
    __syncthreads();

    // coalesced writeback of the 64x64 tile
#pragma unroll
    for (int rep = 0; rep < 16; ++rep) {
        int idx = tid + 256 * rep;
        int g = idx >> 6, ql = idx & 63;
        g_cost[b][g][qbase + ql] = smc[g][ql];
    }
    // per-block row minima: 4 threads per g, packed sign-biased key
    {
        int g = tid >> 2, sub = tid & 3;
        unsigned long long best = ~0ULL;
#pragma unroll
        for (int k = 0; k < 16; ++k) {
            int ql = sub * 16 + k;
            int v = smc[g][ql];
            unsigned long long key =
                ((unsigned long long)((unsigned)v ^ 0x80000000u) << 12) |
                (unsigned)(qbase + ql + 1);
            best = umin64(best, key);
        }
        best = umin64(best, __shfl_down_sync(0xffffffffu, best, 2));
        best = umin64(best, __shfl_down_sync(0xffffffffu, best, 1));
        if (sub == 0) g_blockmin[b][qblk][g] = best;
    }

    // focal-neg partial over this 64-row tile (branch-free formula)
    float acc0 = 0.0f, acc1 = 0.0f;
    const float4* base4 = (const float4*)(cs + ((size_t)(b * QQ + qbase)) * CC);
    for (int idx = tid; idx < QT * (CC / 4); idx += 256) {
        float4 v = __ldg(base4 + idx);
        acc0 += focal_neg_fast(v.x);
        acc1 += focal_neg_fast(v.y);
        acc0 += focal_neg_fast(v.z);
        acc1 += focal_neg_fast(v.w);
    }
    double acc = (double)acc0 + (double)acc1;
    for (int off = 16; off; off >>= 1) acc += __shfl_down_sync(0xffffffffu, acc, off);
    int lane = tid & 31, warp = tid >> 5;
    if (lane == 0) swred[warp] = acc;
    __syncthreads();
    if (tid == 0) {
        double s = 0.0;
        for (int w = 0; w < 8; ++w) s += swred[w];
        g_part_cls[blockIdx.x] = s;
    }
}

// ======== K2: JV LSA (deferred-dual Dijkstra) + bbox epilogue + final ========
__global__ __launch_bounds__(NT) void lsa_kernel(const float* __restrict__ cs,
                                                 const float* __restrict__ bp,
                                                 const int* __restrict__ gl,
                                                 const float* __restrict__ gb,
                                                 float* __restrict__ out) {
    const int b = blockIdx.x, tid = threadIdx.x;
    const int lane = tid & 31, warp = tid >> 5;

    __shared__ long long sv[QQ + 1];
    __shared__ long long sminv[QQ + 1];
    __shared__ long long smark[QQ + 1];          // SD at join per used column
    __shared__ long long su[GG + 1];
    __shared__ short sp[QQ + 1];
    __shared__ short sway[QQ + 1];
    __shared__ short slist[QQ + 1];
    __shared__ unsigned char sstamp[QQ + 1];
    __shared__ short srowarg[GG + 1];
    __shared__ short spend[GG];
    __shared__ short sinv[GG];
    __shared__ unsigned long long sred[NT];
    __shared__ long long rp[NT / 32];
    __shared__ long long sdelta, sSD;
    __shared__ int scnt, sj0, si0, sdone, snpend, slast;

    for (int j = tid; j <= QQ; j += NT) { sv[j] = 0; sp[j] = 0; sstamp[j] = 0; }

    // --- Phase A: reduce per-block row minima (2048 packed u64) ---
    {
        int g = tid & 63, grp = tid >> 6;      // 8 groups of 4 k's
        unsigned long long best = ~0ULL;
#pragma unroll
        for (int k = 0; k < 4; ++k)
            best = umin64(best, __ldg(&g_blockmin[b][grp * 4 + k][g]));
        sred[tid] = best;
    }
    __syncthreads();
    if (tid < GG) {
        unsigned long long m = sred[tid];
#pragma unroll
        for (int j = 1; j < 8; ++j) m = umin64(m, sred[tid + 64 * j]);
        int v = (int)((unsigned)(m >> 12) ^ 0x80000000u);
        su[tid + 1] = (long long)v;
        srowarg[tid + 1] = (short)(m & 4095);
    }
    __syncthreads();

    const int* __restrict__ costb = &g_cost[b][0][0];

    // --- Phase B: greedy assignment on tight edges ---
    if (tid == 0) {
        int np = 0;
        for (int i = 1; i <= GG; ++i) {
            int j = srowarg[i];
            if (sp[j] == 0) sp[j] = (short)i;
            else spend[np++] = (short)i;
        }
        snpend = np;
    }
    __syncthreads();

    // --- Phase C: augment remaining rows (deferred u/v updates, 2 syncs/iter) ---
    const int np = snpend;
    for (int pi = 0; pi < np; ++pi) {
        const int i = spend[pi];
        if (tid == 0) {
            sj0 = 0; si0 = i; scnt = 1; slist[0] = 0; smark[0] = 0;
            sp[0] = (short)i; sdone = 0; sSD = 0;
        }
        __syncthreads();
        bool first = true;
        for (;;) {
            const int i0 = si0, j0c = sj0;
            const long long ui0 = su[i0];                 // phase-start value (deferred)
            const long long dpre = first ? 0 : sdelta;
            const int* arow = costb + (size_t)(i0 - 1) * QQ;
            int av[REPS];
#pragma unroll
            for (int rep = 0; rep < REPS; rep++) av[rep] = __ldg(arow + tid + rep * NT);
            long long best = (1LL << 62);
#pragma unroll
            for (int rep = 0; rep < REPS; rep++) {
                int j = tid + 1 + rep * NT;
                if (sstamp[j] == (unsigned char)i) continue;
                if (j == j0c) { sstamp[j] = (unsigned char)i; continue; }  // mark frontier
                long long mv = first ? INF64 : (sminv[j] - dpre);          // lazy minv-=delta
                long long cur = (long long)av[rep] - ui0 - sv[j];          // sv untouched in-phase
                if (cur < mv) { mv = cur; sway[j] = (short)j0c; }
                sminv[j] = mv;
                long long pk = (mv << 12) | (long long)j;                  // lex (value, j)
                best = (pk < best) ? pk : best;
            }
#pragma unroll
            for (int off = 16; off; off >>= 1) {
                long long o = __shfl_down_sync(0xffffffffu, best, off);
                best = (o < best) ? o : best;
            }
            if (lane == 0) rp[warp] = best;
            __syncthreads();
            if (warp == 0) {
                best = (lane < NT / 32) ? rp[lane] : (1LL << 62);
#pragma unroll
                for (int off = (NT / 64); off; off >>= 1) {
                    long long o = __shfl_down_sync(0xffffffffu, best, off);
                    best = (o < best) ? o : best;
                }
                if (lane == 0) {
                    if (j0c) {                           // append prev frontier col
                        slist[scnt] = (short)j0c;
                        smark[scnt] = sSD;               // SD before this delta
                        scnt = scnt + 1;
                    }
                    long long d = best >> 12;
                    int j1 = (int)(best & 4095);
                    sSD += d;
                    sdelta = d; sj0 = j1; si0 = sp[j1];
                    sdone = (sp[j1] == 0);
                }
            }
            __syncthreads();
            if (sdone) break;
            first = false;
        }
        // deferred u/v updates: entry joined with mark m gets (SDfinal - m)
        const long long SDf = sSD;
        const int cnt = scnt;
        for (int t = tid; t < cnt; t += NT) {
            long long adj = SDf - smark[t];
            int jj = slist[t];
            su[sp[jj]] += adj;                           // pre-augment sp (matches ref order)
            sv[jj] -= adj;
        }
        __syncthreads();
        if (tid == 0) {                                  // augment along way[]
            int j0 = sj0;
            while (j0) { int jn = sway[j0]; sp[j0] = sp[jn]; j0 = jn; }
        }
        __syncthreads();
    }

    // --- build g -> q map in smem ---
#pragma unroll
    for (int rep = 0; rep < REPS; rep++) {
        int j = tid + 1 + rep * NT;
        int pj = sp[j];
        if (pj) sinv[pj - 1] = (short)(j - 1);
    }
    __syncthreads();

    // --- fused bbox losses + argmax acc + focal correction (warp per g) ---
    double sb = 0.0, sx = 0.0, corr = 0.0;
    int ok = 0;
#pragma unroll
    for (int gw = 0; gw < 4; ++gw) {
        int g = gw * 16 + warp;
        int q = sinv[g];
        int lab = gl[b * GG + g];
        const float* r = cs + (size_t)(b * QQ + q) * CC;

        float best = -INFINITY; int bi = 0;
#pragma unroll
        for (int k = 0; k < 4; ++k) {
            int c = lane + 32 * k;
            float v = __ldg(r + c);
            if (v > best) { best = v; bi = c; }
        }
        for (int off = 16; off; off >>= 1) {
            float ov = __shfl_down_sync(0xffffffffu, best, off);
            int   oi = __shfl_down_sync(0xffffffffu, bi, off);
            if (ov > best || (ov == best && oi < bi)) { best = ov; bi = oi; }
        }
        if (lane == 0) ok += (bi == lab) ? 1 : 0;

        if (lane < 10) {
            float a  = bp[(size_t)(b * QQ + q) * 10 + lane];
            float c2 = gb[(size_t)(b * GG + g) * 10 + lane];
            float nr = c_normf[lane];
            sb += (double)fabsf(a / nr - c2 / nr);
            if (lane < 3) sx += (double)fabsf(a - c2);
        }
        if (lane == 0) {            // correction: pos - neg, same formula as fused
            float x = __ldg(r + lab);
            float e = __expf(-x);
            float d0 = 1.0f + e;
            float p = __fdividef(1.0f, d0);
            float lg = __logf(d0);
            float neg = (x + lg) * (0.75f * (p * p));
            float om = 1.0f - p;
            float pos = lg * (0.25f * (om * om));
            corr += (double)pos - (double)neg;
        }
    }
    for (int off = 16; off; off >>= 1) {
        sb   += __shfl_down_sync(0xffffffffu, sb, off);
        sx   += __shfl_down_sync(0xffffffffu, sx, off);
        corr += __shfl_down_sync(0xffffffffu, corr, off);
        ok   += __shfl_down_sync(0xffffffffu, ok, off);
    }
    __shared__ double shb[16], shx[16], shc[16];
    __shared__ int sha[16];
    if (lane == 0) { shb[warp] = sb; shx[warp] = sx; shc[warp] = corr; sha[warp] = ok; }
    __syncthreads();
    if (tid == 0) {
        double tb = 0, tx2 = 0, tc = 0; int ta = 0;
        for (int w = 0; w < 16; ++w) { tb += shb[w]; tx2 += shx[w]; tc += shc[w]; ta += sha[w]; }
        g_part_bbox[b] = tb; g_part_xyz[b] = tx2; g_part_corr[b] = tc; g_part_acc[b] = ta;
    }

    // --- last block performs the final combine (fused final_kernel) ---
    __syncthreads();
    if (tid == 0) {
        __threadfence();
        slast = (atomicAdd(&g_ctr, 1) == BB - 1) ? 1 : 0;
    }
    __syncthreads();
    if (slast) {
        __threadfence();
        double s = 0.0;
        for (int k = tid; k < BB * NQB; k += NT) s += g_part_cls[k];
        double c2 = 0.0, b2 = 0.0, x2 = 0.0, a2 = 0.0;
        if (tid < BB) {
            c2 = g_part_corr[tid]; b2 = g_part_bbox[tid]; x2 = g_part_xyz[tid];
            a2 = (double)g_part_acc[tid];
        }
        for (int off = 16; off; off >>= 1) {
            s  += __shfl_down_sync(0xffffffffu, s, off);
            c2 += __shfl_down_sync(0xffffffffu, c2, off);
            b2 += __shfl_down_sync(0xffffffffu, b2, off);
            x2 += __shfl_down_sync(0xffffffffu, x2, off);
            a2 += __shfl_down_sync(0xffffffffu, a2, off);
        }
        __shared__ double w0[16], w1[16], w2[16], w3[16], w4[16];
        if (lane == 0) { w0[warp] = s; w1[warp] = c2; w2[warp] = b2; w3[warp] = x2; w4[warp] = a2; }
        __syncthreads();
        if (tid == 0) {
            double ts = 0, tc = 0, tb = 0, tx = 0, ta = 0;
            for (int w = 0; w < 16; ++w) {
                ts += w0[w]; tc += w1[w]; tb += w2[w]; tx += w3[w]; ta += w4[w];
            }
            out[0] = (float)((ts + tc) / 4096.0);
            out[1] = (float)(tb / 40960.0);
            out[2] = 64.0f;
            out[3] = (float)(ta / 4096.0);
            out[4] = (float)(tx / 12288.0);
            g_ctr = 0;                       // reset for next graph replay
        }
    }
}

// ---------------- launch ----------------
extern "C" void kernel_launch(void* const* d_in, const int* in_sizes, int n_in,
                              void* d_out, int out_size) {
    const float* cs = (const float*)d_in[0];   // (64,2048,128) f32
    const float* bp = (const float*)d_in[1];   // (64,2048,10)  f32
    const int*   gl = (const int*)d_in[2];     // (64,64)       i32
    const float* gb = (const float*)d_in[3];   // (64,64,10)    f32
    float* out = (float*)d_out;

    fused_kernel<<<BB * NQB, 256>>>(cs, bp, gl, gb);
    lsa_kernel<<<BB, NT>>>(cs, bp, gl, gb, out);
}